// round 1
// baseline (speedup 1.0000x reference)
#include <cuda_runtime.h>

#define NMAX 131072
#define DIN 512
#define DH 128
#define KCB 256

// ---- persistent scratch (device globals: the sanctioned no-alloc workaround) ----
static __device__ float g_lat[NMAX * DH];      // latent = r0
static __device__ float g_rem[NMAX * DH];      // running remainder
static __device__ float g_t[NMAX * DH];        // t = emb @ W_dec
static __device__ float g_B[2 * DH * DIN];     // [W_enc ; W_dec^T] rows, 256 x 512
static __device__ float g_G[DH * DH];          // W_dec^T W_dec
static __device__ float g_cn[3 * KCB];         // codebook squared norms
static __device__ double g_acc[4];             // 0:S_ee 1:cross 2:quad 3:sum|r_next|^2
static __device__ unsigned g_used[3 * 8];      // used-code bitmasks

__device__ __forceinline__ float blk_reduce256(float v, float* sbuf) {
    #pragma unroll
    for (int o = 16; o > 0; o >>= 1) v += __shfl_down_sync(0xffffffffu, v, o);
    int w = threadIdx.x >> 5;
    if ((threadIdx.x & 31) == 0) sbuf[w] = v;
    __syncthreads();
    float r = 0.f;
    if (threadIdx.x == 0) {
        #pragma unroll
        for (int i = 0; i < 8; i++) r += sbuf[i];
    }
    __syncthreads();   // protect sbuf for reuse
    return r;          // valid on thread 0 only
}

__global__ void k_zero() {
    int t = threadIdx.x;
    if (t < 4)  g_acc[t] = 0.0;
    if (t < 24) g_used[t] = 0u;
}

// Build stacked B matrix: rows 0..127 = W_enc rows, rows 128..255 = W_dec^T rows
__global__ void k_prep(const float* __restrict__ Wenc, const float* __restrict__ Wdec) {
    int r = blockIdx.x;
    for (int i = threadIdx.x; i < DIN; i += blockDim.x)
        g_B[r * DIN + i] = (r < DH) ? Wenc[r * DIN + i] : Wdec[i * DH + (r - DH)];
}

// G = W_dec^T W_dec  (128x128, K=512)
__global__ void k_G(const float* __restrict__ Wdec) {
    int h1 = blockIdx.x, h2 = threadIdx.x;
    float s = 0.f;
    for (int i = 0; i < DIN; i++)
        s = fmaf(__ldg(&Wdec[i * DH + h1]), __ldg(&Wdec[i * DH + h2]), s);
    g_G[h1 * DH + h2] = s;
}

__global__ void k_cnorm(const float* __restrict__ cb0, const float* __restrict__ cb1,
                        const float* __restrict__ cb2) {
    const float* cb = (blockIdx.x == 0) ? cb0 : ((blockIdx.x == 1) ? cb1 : cb2);
    int c = threadIdx.x;
    float s = 0.f;
    for (int d = 0; d < DH; d++) { float v = __ldg(&cb[c * DH + d]); s = fmaf(v, v, s); }
    g_cn[blockIdx.x * KCB + c] = s;
}

// C[N,256] = emb[N,512] @ g_B^T. Writes latent (cols 0..127) to g_lat & g_rem,
// t (cols 128..255) to g_t. Accumulates S_ee.
__global__ __launch_bounds__(256) void k_gemm(const float* __restrict__ A) {
    __shared__ float As[16][68];    // stride 68 floats: 16B-aligned rows
    __shared__ float Bs[16][256];
    __shared__ float sred[8];
    int tid = threadIdx.x;
    int tx = tid & 31, ty = tid >> 5;
    int m0 = blockIdx.x * 64;
    int arow = tid >> 2, ak = (tid & 3) * 4;

    float acc[8][8];
    #pragma unroll
    for (int i = 0; i < 8; i++)
        #pragma unroll
        for (int j = 0; j < 8; j++) acc[i][j] = 0.f;
    float see = 0.f;

    for (int k0 = 0; k0 < DIN; k0 += 16) {
        float4 av = *(const float4*)(A + (size_t)(m0 + arow) * DIN + k0 + ak);
        As[ak + 0][arow] = av.x; As[ak + 1][arow] = av.y;
        As[ak + 2][arow] = av.z; As[ak + 3][arow] = av.w;
        see += av.x * av.x + av.y * av.y + av.z * av.z + av.w * av.w;
        #pragma unroll
        for (int u = 0; u < 4; u++) {
            float4 bv = *(const float4*)(g_B + (size_t)tid * DIN + k0 + u * 4);
            Bs[u * 4 + 0][tid] = bv.x; Bs[u * 4 + 1][tid] = bv.y;
            Bs[u * 4 + 2][tid] = bv.z; Bs[u * 4 + 3][tid] = bv.w;
        }
        __syncthreads();
        #pragma unroll
        for (int k = 0; k < 16; k++) {
            float a[8], b[8];
            *(float4*)&a[0] = *(float4*)&As[k][ty * 8];
            *(float4*)&a[4] = *(float4*)&As[k][ty * 8 + 4];
            *(float4*)&b[0] = *(float4*)&Bs[k][tx * 8];
            *(float4*)&b[4] = *(float4*)&Bs[k][tx * 8 + 4];
            #pragma unroll
            for (int i = 0; i < 8; i++)
                #pragma unroll
                for (int j = 0; j < 8; j++) acc[i][j] = fmaf(a[i], b[j], acc[i][j]);
        }
        __syncthreads();
    }

    #pragma unroll
    for (int i = 0; i < 8; i++) {
        int n = m0 + ty * 8 + i;
        float4 v0 = make_float4(acc[i][0], acc[i][1], acc[i][2], acc[i][3]);
        float4 v1 = make_float4(acc[i][4], acc[i][5], acc[i][6], acc[i][7]);
        if (tx < 16) {
            int c = tx * 8;
            *(float4*)(g_lat + (size_t)n * DH + c)     = v0;
            *(float4*)(g_lat + (size_t)n * DH + c + 4) = v1;
            *(float4*)(g_rem + (size_t)n * DH + c)     = v0;
            *(float4*)(g_rem + (size_t)n * DH + c + 4) = v1;
        } else {
            int c = tx * 8 - 128;
            *(float4*)(g_t + (size_t)n * DH + c)     = v0;
            *(float4*)(g_t + (size_t)n * DH + c + 4) = v1;
        }
    }
    float tot = blk_reduce256(see, sred);
    if (tid == 0) atomicAdd(&g_acc[0], (double)tot);
}

// One RQ stage: scores = |c|^2 - 2 r.c over 64 samples x 256 codes, argmin,
// remainder update, |r_next|^2 accumulation, used-bit marking.
__global__ __launch_bounds__(256) void k_stage(const float* __restrict__ cb, int stage) {
    __shared__ float As[16][68];
    __shared__ float Bs[16][256];
    __shared__ float cn[256];
    __shared__ float sVal[64][33];
    __shared__ int   sIdx[64][33];
    __shared__ int   sChosen[64];
    __shared__ unsigned sMask[8];
    __shared__ float sred[8];

    int tid = threadIdx.x;
    int tx = tid & 31, ty = tid >> 5;
    int m0 = blockIdx.x * 64;
    if (tid < 8) sMask[tid] = 0u;
    cn[tid] = g_cn[stage * KCB + tid];
    int arow = tid >> 2, ak = (tid & 3) * 4;

    float acc[8][8];
    #pragma unroll
    for (int i = 0; i < 8; i++)
        #pragma unroll
        for (int j = 0; j < 8; j++) acc[i][j] = 0.f;

    for (int k0 = 0; k0 < DH; k0 += 16) {
        float4 av = *(const float4*)(g_rem + (size_t)(m0 + arow) * DH + k0 + ak);
        As[ak + 0][arow] = av.x; As[ak + 1][arow] = av.y;
        As[ak + 2][arow] = av.z; As[ak + 3][arow] = av.w;
        #pragma unroll
        for (int u = 0; u < 4; u++) {
            float4 bv = *(const float4*)(cb + (size_t)tid * DH + k0 + u * 4);
            Bs[u * 4 + 0][tid] = bv.x; Bs[u * 4 + 1][tid] = bv.y;
            Bs[u * 4 + 2][tid] = bv.z; Bs[u * 4 + 3][tid] = bv.w;
        }
        __syncthreads();
        #pragma unroll
        for (int k = 0; k < 16; k++) {
            float a[8], b[8];
            *(float4*)&a[0] = *(float4*)&As[k][ty * 8];
            *(float4*)&a[4] = *(float4*)&As[k][ty * 8 + 4];
            *(float4*)&b[0] = *(float4*)&Bs[k][tx * 8];
            *(float4*)&b[4] = *(float4*)&Bs[k][tx * 8 + 4];
            #pragma unroll
            for (int i = 0; i < 8; i++)
                #pragma unroll
                for (int j = 0; j < 8; j++) acc[i][j] = fmaf(a[i], b[j], acc[i][j]);
        }
        __syncthreads();
    }

    // per-thread argmin (codes ascend with j -> strict < keeps first index)
    #pragma unroll
    for (int i = 0; i < 8; i++) {
        float bv = 3.402823466e38f; int bj = 0;
        #pragma unroll
        for (int j = 0; j < 8; j++) {
            float v = cn[tx * 8 + j] - 2.f * acc[i][j];
            if (v < bv) { bv = v; bj = tx * 8 + j; }
        }
        sVal[ty * 8 + i][tx] = bv;
        sIdx[ty * 8 + i][tx] = bj;
    }
    __syncthreads();

    if (tid < 64) {
        float bv = sVal[tid][0]; int bi = sIdx[tid][0];
        #pragma unroll
        for (int t = 1; t < 32; t++) {
            float v = sVal[tid][t];                 // tx ascends => codes ascend
            if (v < bv) { bv = v; bi = sIdx[tid][t]; }
        }
        sChosen[tid] = bi;
        atomicOr(&sMask[bi >> 5], 1u << (bi & 31));
    }
    __syncthreads();

    // remainder update + |r_next|^2
    int s = tid >> 2;
    int n = m0 + s;
    int code = sChosen[s];
    int dbase = (tid & 3) * 32;
    float r2 = 0.f;
    #pragma unroll
    for (int d = 0; d < 32; d += 4) {
        int dd = dbase + d;
        float4 r = *(float4*)(g_rem + (size_t)n * DH + dd);
        float4 c = *(const float4*)(cb + (size_t)code * DH + dd);
        r.x -= c.x; r.y -= c.y; r.z -= c.z; r.w -= c.w;
        r2 += r.x * r.x + r.y * r.y + r.z * r.z + r.w * r.w;
        *(float4*)(g_rem + (size_t)n * DH + dd) = r;
    }
    float tot = blk_reduce256(r2, sred);
    if (tid == 0) atomicAdd(&g_acc[3], (double)tot);
    if (tid < 8 && sMask[tid]) atomicOr(&g_used[stage * 8 + tid], sMask[tid]);
}

// cross = sum <t, res>, quad = sum res^T G res (via per-block Mb = R^T R, <G,Mb>)
__global__ __launch_bounds__(256) void k_fin() {
    __shared__ float Rs[64][128];
    __shared__ float sred[8];
    int tid = threadIdx.x;
    int m0 = blockIdx.x * 64;
    float cross = 0.f;
    #pragma unroll
    for (int i = 0; i < 32; i++) {
        int idx = tid + i * 256;
        float R = g_lat[(size_t)m0 * DH + idx] - g_rem[(size_t)m0 * DH + idx];
        Rs[idx >> 7][idx & 127] = R;
        cross += g_t[(size_t)m0 * DH + idx] * R;
    }
    __syncthreads();

    int ty = tid >> 4, tx = tid & 15;   // Mb tile: rows a=ty*8.., cols b=tx*8..
    float acc[8][8];
    #pragma unroll
    for (int i = 0; i < 8; i++)
        #pragma unroll
        for (int j = 0; j < 8; j++) acc[i][j] = 0.f;
    for (int s = 0; s < 64; s++) {
        float a[8], b[8];
        *(float4*)&a[0] = *(float4*)&Rs[s][ty * 8];
        *(float4*)&a[4] = *(float4*)&Rs[s][ty * 8 + 4];
        *(float4*)&b[0] = *(float4*)&Rs[s][tx * 8];
        *(float4*)&b[4] = *(float4*)&Rs[s][tx * 8 + 4];
        #pragma unroll
        for (int i = 0; i < 8; i++)
            #pragma unroll
            for (int j = 0; j < 8; j++) acc[i][j] = fmaf(a[i], b[j], acc[i][j]);
    }
    float quad = 0.f;
    #pragma unroll
    for (int i = 0; i < 8; i++)
        #pragma unroll
        for (int j = 0; j < 8; j++)
            quad += acc[i][j] * __ldg(&g_G[(ty * 8 + i) * DH + tx * 8 + j]);

    float c = blk_reduce256(cross, sred);
    if (tid == 0) atomicAdd(&g_acc[1], (double)c);
    float q = blk_reduce256(quad, sred);
    if (tid == 0) atomicAdd(&g_acc[2], (double)q);
}

__global__ void k_out(float* out, int out_size, int N) {
    int t = threadIdx.x;
    for (int i = t; i < out_size; i += blockDim.x) out[i] = 0.f;
    __syncthreads();
    if (t == 0) {
        double see = g_acc[0], cross = g_acc[1], quad = g_acc[2], r2 = g_acc[3];
        double recon = (see - 2.0 * cross + quad) / ((double)N * (double)DIN);
        double rq = 1.25 * r2 / ((double)N * (double)DH);
        double loss = recon + rq;
        int u[3];
        #pragma unroll
        for (int s = 0; s < 3; s++) {
            int c = 0;
            #pragma unroll
            for (int w = 0; w < 8; w++) c += __popc(g_used[s * 8 + w]);
            u[s] = c;
        }
        if (out_size > 0) out[0] = (float)loss;
        if (out_size > 1) out[1] = (float)recon;
        if (out_size > 2) out[2] = (float)rq;
        if (out_size > 3) out[3] = (float)u[0];
        if (out_size > 4) out[4] = (float)u[1];
        if (out_size > 5) out[5] = (float)u[2];
    }
}

extern "C" void kernel_launch(void* const* d_in, const int* in_sizes, int n_in,
                              void* d_out, int out_size) {
    const float* emb  = (const float*)d_in[0];
    const float* Wenc = (const float*)d_in[1];
    const float* Wdec = (const float*)d_in[2];
    const float* cb0  = (const float*)d_in[3];
    const float* cb1  = (const float*)d_in[4];
    const float* cb2  = (const float*)d_in[5];
    int N = in_sizes[0] / DIN;
    if (N > NMAX) N = NMAX;
    int nb = N / 64;

    k_zero<<<1, 64>>>();
    k_prep<<<256, 128>>>(Wenc, Wdec);
    k_G<<<128, 128>>>(Wdec);
    k_cnorm<<<3, 256>>>(cb0, cb1, cb2);
    k_gemm<<<nb, 256>>>(emb);
    k_stage<<<nb, 256>>>(cb0, 0);
    k_stage<<<nb, 256>>>(cb1, 1);
    k_stage<<<nb, 256>>>(cb2, 2);
    k_fin<<<nb, 256>>>();
    k_out<<<1, 32>>>((float*)d_out, out_size, N);
}

// round 5
// speedup vs baseline: 2.1288x; 2.1288x over previous
#include <cuda_runtime.h>
#include <cuda_bf16.h>
#include <cstdint>

#define NMAX 131072
#define DIN 512
#define DH 128
#define KCB 256

// ---------------- persistent scratch ----------------
static __device__ float g_lat[(size_t)NMAX * DH];
static __device__ float g_rem[(size_t)NMAX * DH];
static __device__ float g_t[(size_t)NMAX * DH];
static __device__ __nv_bfloat16 g_Bhi[2 * DH * DIN];
static __device__ __nv_bfloat16 g_Blo[2 * DH * DIN];
static __device__ __nv_bfloat16 g_cbhi[3 * KCB * DH];
static __device__ __nv_bfloat16 g_cblo[3 * KCB * DH];
static __device__ float g_G[DH * DH];
static __device__ __nv_bfloat16 g_Ghi[DH * DH];
static __device__ __nv_bfloat16 g_Glo[DH * DH];
static __device__ float g_cn[3 * KCB];
static __device__ double g_acc[4];      // 0:S_ee 1:cross 2:quad 3:sum|r_next|^2
static __device__ unsigned g_used[24];

// ---------------- helpers ----------------
__device__ __forceinline__ uint32_t smem_u32(const void* p) {
    uint32_t a;
    asm("{ .reg .u64 t; cvta.to.shared.u64 t, %1; cvt.u32.u64 %0, t; }" : "=r"(a) : "l"(p));
    return a;
}
static __device__ __forceinline__ uint32_t SW128(uint32_t x) { return x ^ ((x >> 3) & 0x70u); }

__device__ __forceinline__ void ldm_x4(uint32_t* r, uint32_t addr) {
    asm volatile("ldmatrix.sync.aligned.m8n8.x4.shared.b16 {%0,%1,%2,%3}, [%4];"
                 : "=r"(r[0]), "=r"(r[1]), "=r"(r[2]), "=r"(r[3]) : "r"(addr));
}
__device__ __forceinline__ void mma16816(float* c, const uint32_t* a, const uint32_t* b) {
    asm volatile(
        "mma.sync.aligned.m16n8k16.row.col.f32.bf16.bf16.f32 "
        "{%0,%1,%2,%3}, {%4,%5,%6,%7}, {%8,%9}, {%0,%1,%2,%3};"
        : "+f"(c[0]), "+f"(c[1]), "+f"(c[2]), "+f"(c[3])
        : "r"(a[0]), "r"(a[1]), "r"(a[2]), "r"(a[3]), "r"(b[0]), "r"(b[1]));
}

__device__ __forceinline__ float blk_reduce256(float v, float* sbuf) {
    #pragma unroll
    for (int o = 16; o > 0; o >>= 1) v += __shfl_down_sync(0xffffffffu, v, o);
    int w = threadIdx.x >> 5;
    if ((threadIdx.x & 31) == 0) sbuf[w] = v;
    __syncthreads();
    float r = 0.f;
    if (threadIdx.x == 0) {
        #pragma unroll
        for (int i = 0; i < 8; i++) r += sbuf[i];
    }
    __syncthreads();
    return r;
}

__device__ __forceinline__ void cvt8(float4 a, float4 b, uint32_t* hi, uint32_t* lo) {
    float f[8] = {a.x, a.y, a.z, a.w, b.x, b.y, b.z, b.w};
    unsigned short h[8], l[8];
    #pragma unroll
    for (int i = 0; i < 8; i++) {
        __nv_bfloat16 hb = __float2bfloat16(f[i]);
        __nv_bfloat16 lb = __float2bfloat16(f[i] - __bfloat162float(hb));
        h[i] = __bfloat16_as_ushort(hb);
        l[i] = __bfloat16_as_ushort(lb);
    }
    #pragma unroll
    for (int i = 0; i < 4; i++) {
        hi[i] = (uint32_t)h[2 * i] | ((uint32_t)h[2 * i + 1] << 16);
        lo[i] = (uint32_t)l[2 * i] | ((uint32_t)l[2 * i + 1] << 16);
    }
}

// warp computes 32x64 tile of a 128x128 block GEMM over one K=64 chunk.
// A,B smem tiles: [128 rows][64 bf16], SW128-swizzled, 128B rows.
// 3-term hi/lo split accumulated into c.
__device__ __forceinline__ void warp_mma_chunk(
    float (&c)[2][8][4],
    uint32_t aHi, uint32_t aLo, uint32_t bHi, uint32_t bLo,
    int wm, int wn, int lane)
{
    #pragma unroll
    for (int ks = 0; ks < 4; ks++) {
        const int k0 = ks * 16;
        uint32_t ah[2][4], al[2][4];
        #pragma unroll
        for (int mi = 0; mi < 2; mi++) {
            int row = wm * 32 + mi * 16 + (lane & 15);
            int kk = k0 + ((lane >> 4) << 3);
            uint32_t off = SW128((uint32_t)(row * 128 + kk * 2));
            ldm_x4(ah[mi], aHi + off);
            ldm_x4(al[mi], aLo + off);
        }
        #pragma unroll
        for (int p = 0; p < 4; p++) {
            int grp = lane >> 3;
            int nrow = wn * 64 + p * 16 + ((grp >> 1) << 3) + (lane & 7);
            int kk = k0 + ((grp & 1) << 3);
            uint32_t off = SW128((uint32_t)(nrow * 128 + kk * 2));
            uint32_t bh[4], bl[4];
            ldm_x4(bh, bHi + off);
            ldm_x4(bl, bLo + off);
            #pragma unroll
            for (int mi = 0; mi < 2; mi++) {
                #pragma unroll
                for (int t = 0; t < 2; t++) {
                    mma16816(c[mi][p * 2 + t], ah[mi], &bh[2 * t]);
                    mma16816(c[mi][p * 2 + t], ah[mi], &bl[2 * t]);
                    mma16816(c[mi][p * 2 + t], al[mi], &bh[2 * t]);
                }
            }
        }
    }
}

// ---------------- smem layouts ----------------
#define G1_AHI 0
#define G1_ALO 16384
#define G1_BHI 32768
#define G1_BLO 49152
#define G1_SCL 65536
#define SMEM_G1 (65536 + 64)

#define ST_AHI 0          // 2 chunks of 16K
#define ST_ALO 32768
#define ST_BHI 65536
#define ST_BLO 81920
#define ST_SCL 98304      // scn 1024 | pv 1024 | pi 1024 | chosen 512 | smask 32 | sred 32
#define SMEM_ST (98304 + 3648)

#define FN_AHI 0          // 2 chunks of 16K
#define FN_ALO 32768
#define FN_BHI 65536
#define FN_BLO 81920
#define FN_RES 98304      // 128*129*4 = 66048
#define FN_SCL (98304 + 66048)
#define SMEM_FN (98304 + 66048 + 64)

// ---------------- small prep kernels ----------------
__global__ void k_zero() {
    int t = threadIdx.x;
    if (t < 4)  g_acc[t] = 0.0;
    if (t < 24) g_used[t] = 0u;
}

__global__ void k_prepB(const float* __restrict__ Wenc, const float* __restrict__ Wdec) {
    int r = blockIdx.x;
    for (int i = threadIdx.x; i < DIN; i += blockDim.x) {
        float v = (r < DH) ? Wenc[r * DIN + i] : Wdec[i * DH + (r - DH)];
        __nv_bfloat16 hb = __float2bfloat16(v);
        g_Bhi[r * DIN + i] = hb;
        g_Blo[r * DIN + i] = __float2bfloat16(v - __bfloat162float(hb));
    }
}

__global__ void k_prepCB(const float* __restrict__ cb0, const float* __restrict__ cb1,
                         const float* __restrict__ cb2) {
    int b = blockIdx.x;
    int s = b >> 8, c = b & 255;
    const float* cb = (s == 0) ? cb0 : ((s == 1) ? cb1 : cb2);
    int d = threadIdx.x;
    float v = cb[c * DH + d];
    __nv_bfloat16 hb = __float2bfloat16(v);
    g_cbhi[(s * KCB + c) * DH + d] = hb;
    g_cblo[(s * KCB + c) * DH + d] = __float2bfloat16(v - __bfloat162float(hb));
}

__global__ void k_cnorm(const float* __restrict__ cb0, const float* __restrict__ cb1,
                        const float* __restrict__ cb2) {
    const float* cb = (blockIdx.x == 0) ? cb0 : ((blockIdx.x == 1) ? cb1 : cb2);
    int c = threadIdx.x;
    float s = 0.f;
    for (int d = 0; d < DH; d++) { float v = __ldg(&cb[c * DH + d]); s = fmaf(v, v, s); }
    g_cn[blockIdx.x * KCB + c] = s;
}

__global__ void k_G(const float* __restrict__ Wdec) {
    int h1 = blockIdx.x, h2 = threadIdx.x;
    float s = 0.f;
    for (int i = 0; i < DIN; i++)
        s = fmaf(__ldg(&Wdec[i * DH + h1]), __ldg(&Wdec[i * DH + h2]), s);
    g_G[h1 * DH + h2] = s;
}

__global__ void k_cvtG() {
    int r = blockIdx.x, c = threadIdx.x;
    float v = g_G[r * DH + c];
    __nv_bfloat16 hb = __float2bfloat16(v);
    g_Ghi[r * DH + c] = hb;
    g_Glo[r * DH + c] = __float2bfloat16(v - __bfloat162float(hb));
}

// ---------------- GEMM1: [lat | t] = emb @ [Wenc; Wdec^T]^T ----------------
// grid (nb, 2): blockIdx.y selects output half (0: latent, 1: t)
__global__ __launch_bounds__(256, 2) void k_gemm1(const float* __restrict__ emb) {
    extern __shared__ char S[];
    uint32_t sbase = smem_u32(S);
    int tid = threadIdx.x, wid = tid >> 5, lane = tid & 31;
    int wm = wid >> 1, wn = wid & 1;
    int m0 = blockIdx.x * 128;
    int cy = blockIdx.y;

    float c[2][8][4];
    #pragma unroll
    for (int a = 0; a < 2; a++)
        #pragma unroll
        for (int b = 0; b < 8; b++)
            #pragma unroll
            for (int d = 0; d < 4; d++) c[a][b][d] = 0.f;
    float see = 0.f;

    for (int ch = 0; ch < 8; ch++) {
        if (ch) __syncthreads();     // previous compute done before overwrite
        int k0 = ch * 64;
        #pragma unroll
        for (int i = 0; i < 4; i++) {               // A: 128x64 fp32 -> hi/lo
            int g = tid + 256 * i;
            int row = g >> 3, cg = (g & 7) * 8;
            const float* src = emb + (size_t)(m0 + row) * DIN + k0 + cg;
            float4 v0 = *(const float4*)src;
            float4 v1 = *(const float4*)(src + 4);
            if (cy == 0)
                see += v0.x * v0.x + v0.y * v0.y + v0.z * v0.z + v0.w * v0.w
                     + v1.x * v1.x + v1.y * v1.y + v1.z * v1.z + v1.w * v1.w;
            uint32_t hi[4], lo[4];
            cvt8(v0, v1, hi, lo);
            uint32_t off = SW128((uint32_t)(row * 128 + cg * 2));
            *(uint4*)(S + G1_AHI + off) = make_uint4(hi[0], hi[1], hi[2], hi[3]);
            *(uint4*)(S + G1_ALO + off) = make_uint4(lo[0], lo[1], lo[2], lo[3]);
        }
        #pragma unroll
        for (int i = 0; i < 4; i++) {               // B: rows cy*128.. of stacked W
            int g = tid + 256 * i;
            int row = g >> 3, cg = (g & 7) * 8;
            uint32_t off = SW128((uint32_t)(row * 128 + cg * 2));
            size_t e = (size_t)(cy * 128 + row) * DIN + k0 + cg;
            *(uint4*)(S + G1_BHI + off) = *(const uint4*)((const char*)g_Bhi + e * 2);
            *(uint4*)(S + G1_BLO + off) = *(const uint4*)((const char*)g_Blo + e * 2);
        }
        __syncthreads();
        warp_mma_chunk(c, sbase + G1_AHI, sbase + G1_ALO, sbase + G1_BHI, sbase + G1_BLO,
                       wm, wn, lane);
    }

    // epilogue: write C
    int rl = wm * 32 + (lane >> 2);
    int nc = wn * 64 + (lane & 3) * 2;
    #pragma unroll
    for (int mi = 0; mi < 2; mi++) {
        #pragma unroll
        for (int nj = 0; nj < 8; nj++) {
            int r0 = m0 + rl + mi * 16;
            int n = nc + nj * 8;
            float2 vlo = make_float2(c[mi][nj][0], c[mi][nj][1]);
            float2 vhi = make_float2(c[mi][nj][2], c[mi][nj][3]);
            if (cy == 0) {
                *(float2*)(g_lat + (size_t)r0 * DH + n) = vlo;
                *(float2*)(g_rem + (size_t)r0 * DH + n) = vlo;
                *(float2*)(g_lat + (size_t)(r0 + 8) * DH + n) = vhi;
                *(float2*)(g_rem + (size_t)(r0 + 8) * DH + n) = vhi;
            } else {
                *(float2*)(g_t + (size_t)r0 * DH + n) = vlo;
                *(float2*)(g_t + (size_t)(r0 + 8) * DH + n) = vhi;
            }
        }
    }
    if (cy == 0) {
        float tot = blk_reduce256(see, (float*)(S + G1_SCL));
        if (tid == 0) atomicAdd(&g_acc[0], (double)tot);
    }
}

// ---------------- RQ stage ----------------
__global__ __launch_bounds__(256, 2) void k_stage(const float* __restrict__ cb, int stage) {
    extern __shared__ char S[];
    uint32_t sbase = smem_u32(S);
    int tid = threadIdx.x, wid = tid >> 5, lane = tid & 31;
    int wm = wid >> 1, wn = wid & 1;
    int m0 = blockIdx.x * 128;

    float* scn = (float*)(S + ST_SCL);
    float* pv = (float*)(S + ST_SCL + 1024);
    int* pi = (int*)(S + ST_SCL + 2048);
    int* chosen = (int*)(S + ST_SCL + 3072);
    unsigned* smask = (unsigned*)(S + ST_SCL + 3584);
    float* sred = (float*)(S + ST_SCL + 3616);

    scn[tid] = g_cn[stage * KCB + tid];
    if (tid < 8) smask[tid] = 0u;

    #pragma unroll
    for (int i = 0; i < 8; i++) {                   // A = remainder 128x128 fp32 -> hi/lo
        int g = tid + 256 * i;
        int row = g >> 4, cg = (g & 15) * 8;
        const float* src = g_rem + (size_t)(m0 + row) * DH + cg;
        float4 v0 = *(const float4*)src;
        float4 v1 = *(const float4*)(src + 4);
        uint32_t hi[4], lo[4];
        cvt8(v0, v1, hi, lo);
        uint32_t off = (uint32_t)(cg >> 6) * 16384u + SW128((uint32_t)(row * 128 + (cg & 63) * 2));
        *(uint4*)(S + ST_AHI + off) = make_uint4(hi[0], hi[1], hi[2], hi[3]);
        *(uint4*)(S + ST_ALO + off) = make_uint4(lo[0], lo[1], lo[2], lo[3]);
    }

    float best[4] = {3.402823466e38f, 3.402823466e38f, 3.402823466e38f, 3.402823466e38f};
    int bidx[4] = {0, 0, 0, 0};

    for (int hh = 0; hh < 2; hh++) {                // codebook halves (128 codes each)
        float c[2][8][4];
        #pragma unroll
        for (int a = 0; a < 2; a++)
            #pragma unroll
            for (int b = 0; b < 8; b++)
                #pragma unroll
                for (int d = 0; d < 4; d++) c[a][b][d] = 0.f;

        for (int kc = 0; kc < 2; kc++) {
            __syncthreads();                        // also covers initial A/scn visibility
            #pragma unroll
            for (int i = 0; i < 4; i++) {           // B = codebook chunk 128x64 bf16
                int g = tid + 256 * i;
                int row = g >> 3, cg = (g & 7) * 8;
                uint32_t off = SW128((uint32_t)(row * 128 + cg * 2));
                size_t e = (size_t)(stage * KCB + hh * 128 + row) * DH + kc * 64 + cg;
                *(uint4*)(S + ST_BHI + off) = *(const uint4*)((const char*)g_cbhi + e * 2);
                *(uint4*)(S + ST_BLO + off) = *(const uint4*)((const char*)g_cblo + e * 2);
            }
            __syncthreads();
            warp_mma_chunk(c, sbase + ST_AHI + kc * 16384, sbase + ST_ALO + kc * 16384,
                           sbase + ST_BHI, sbase + ST_BLO, wm, wn, lane);
        }
        // per-lane argmin update (ng ascends within lane -> strict < keeps first)
        #pragma unroll
        for (int mi = 0; mi < 2; mi++) {
            #pragma unroll
            for (int nj = 0; nj < 8; nj++) {
                int n = wn * 64 + nj * 8 + (lane & 3) * 2;
                int ng = hh * 128 + n;
                float cn0 = scn[ng], cn1 = scn[ng + 1];
                float v0 = cn0 - 2.f * c[mi][nj][0];
                float v1 = cn1 - 2.f * c[mi][nj][1];
                float v2 = cn0 - 2.f * c[mi][nj][2];
                float v3 = cn1 - 2.f * c[mi][nj][3];
                int s0 = mi * 2, s1 = mi * 2 + 1;
                if (v0 < best[s0]) { best[s0] = v0; bidx[s0] = ng; }
                if (v1 < best[s0]) { best[s0] = v1; bidx[s0] = ng + 1; }
                if (v2 < best[s1]) { best[s1] = v2; bidx[s1] = ng; }
                if (v3 < best[s1]) { best[s1] = v3; bidx[s1] = ng + 1; }
            }
        }
    }

    // cross-lane reduce (lanes sharing a row differ in lane&3); tie -> lower index
    #pragma unroll
    for (int q = 0; q < 4; q++) {
        float v = best[q]; int ix = bidx[q];
        #pragma unroll
        for (int o = 1; o <= 2; o <<= 1) {
            float vo = __shfl_xor_sync(0xffffffffu, v, o);
            int io = __shfl_xor_sync(0xffffffffu, ix, o);
            if (vo < v || (vo == v && io < ix)) { v = vo; ix = io; }
        }
        if ((lane & 3) == 0) {
            int row = wm * 32 + (q >> 1) * 16 + (q & 1) * 8 + (lane >> 2);
            pv[row * 2 + wn] = v;
            pi[row * 2 + wn] = ix;
        }
    }
    __syncthreads();
    if (tid < 128) {
        float v0 = pv[tid * 2], v1 = pv[tid * 2 + 1];
        int i0 = pi[tid * 2], i1 = pi[tid * 2 + 1];
        int idx = (v1 < v0 || (v1 == v0 && i1 < i0)) ? i1 : i0;
        chosen[tid] = idx;
        atomicOr(&smask[idx >> 5], 1u << (idx & 31));
    }
    __syncthreads();

    // remainder update + |r_next|^2
    int rr = tid >> 1, part = tid & 1;
    int code = chosen[rr];
    const float* crow = cb + (size_t)code * DH + part * 64;
    float* rrow = g_rem + (size_t)(m0 + rr) * DH + part * 64;
    float r2 = 0.f;
    #pragma unroll
    for (int d = 0; d < 64; d += 4) {
        float4 rv = *(float4*)(rrow + d);
        float4 cv = *(const float4*)(crow + d);
        rv.x -= cv.x; rv.y -= cv.y; rv.z -= cv.z; rv.w -= cv.w;
        r2 += rv.x * rv.x + rv.y * rv.y + rv.z * rv.z + rv.w * rv.w;
        *(float4*)(rrow + d) = rv;
    }
    float tot = blk_reduce256(r2, sred);
    if (tid == 0) atomicAdd(&g_acc[3], (double)tot);
    if (tid < 8 && smask[tid]) atomicOr(&g_used[stage * 8 + tid], smask[tid]);
}

// ---------------- fin: cross = sum<t,res>, quad = sum res^T G res ----------------
__global__ __launch_bounds__(256, 1) void k_fin() {
    extern __shared__ char S[];
    uint32_t sbase = smem_u32(S);
    int tid = threadIdx.x, wid = tid >> 5, lane = tid & 31;
    int wm = wid >> 1, wn = wid & 1;
    int m0 = blockIdx.x * 128;

    float* sres = (float*)(S + FN_RES);
    float* sred = (float*)(S + FN_SCL);

    float cross = 0.f;
    #pragma unroll
    for (int i = 0; i < 8; i++) {                   // res fill + convert
        int g = tid + 256 * i;
        int row = g >> 4, cg = (g & 15) * 8;
        size_t idx = (size_t)(m0 + row) * DH + cg;
        float4 l0 = *(const float4*)(g_lat + idx), l1 = *(const float4*)(g_lat + idx + 4);
        float4 r0 = *(const float4*)(g_rem + idx), r1 = *(const float4*)(g_rem + idx + 4);
        float4 t0 = *(const float4*)(g_t + idx),   t1 = *(const float4*)(g_t + idx + 4);
        float4 a = make_float4(l0.x - r0.x, l0.y - r0.y, l0.z - r0.z, l0.w - r0.w);
        float4 b = make_float4(l1.x - r1.x, l1.y - r1.y, l1.z - r1.z, l1.w - r1.w);
        cross += t0.x * a.x + t0.y * a.y + t0.z * a.z + t0.w * a.w
               + t1.x * b.x + t1.y * b.y + t1.z * b.z + t1.w * b.w;
        float* d = sres + row * 129 + cg;
        d[0] = a.x; d[1] = a.y; d[2] = a.z; d[3] = a.w;
        d[4] = b.x; d[5] = b.y; d[6] = b.z; d[7] = b.w;
        uint32_t hi[4], lo[4];
        cvt8(a, b, hi, lo);
        uint32_t off = (uint32_t)(cg >> 6) * 16384u + SW128((uint32_t)(row * 128 + (cg & 63) * 2));
        *(uint4*)(S + FN_AHI + off) = make_uint4(hi[0], hi[1], hi[2], hi[3]);
        *(uint4*)(S + FN_ALO + off) = make_uint4(lo[0], lo[1], lo[2], lo[3]);
    }

    float c[2][8][4];
    #pragma unroll
    for (int a = 0; a < 2; a++)
        #pragma unroll
        for (int b = 0; b < 8; b++)
            #pragma unroll
            for (int d = 0; d < 4; d++) c[a][b][d] = 0.f;

    for (int kc = 0; kc < 2; kc++) {
        __syncthreads();
        #pragma unroll
        for (int i = 0; i < 4; i++) {               // B = G chunk 128x64
            int g = tid + 256 * i;
            int row = g >> 3, cg = (g & 7) * 8;
            uint32_t off = SW128((uint32_t)(row * 128 + cg * 2));
            size_t e = (size_t)row * DH + kc * 64 + cg;
            *(uint4*)(S + FN_BHI + off) = *(const uint4*)((const char*)g_Ghi + e * 2);
            *(uint4*)(S + FN_BLO + off) = *(const uint4*)((const char*)g_Glo + e * 2);
        }
        __syncthreads();
        warp_mma_chunk(c, sbase + FN_AHI + kc * 16384, sbase + FN_ALO + kc * 16384,
                       sbase + FN_BHI, sbase + FN_BLO, wm, wn, lane);
    }

    // quad = sum_{m,n} D[m][n] * res[m][n]
    float quad = 0.f;
    int rl = wm * 32 + (lane >> 2);
    int nc = wn * 64 + (lane & 3) * 2;
    #pragma unroll
    for (int mi = 0; mi < 2; mi++) {
        #pragma unroll
        for (int nj = 0; nj < 8; nj++) {
            int lr = rl + mi * 16;
            int n = nc + nj * 8;
            quad += c[mi][nj][0] * sres[lr * 129 + n]
                  + c[mi][nj][1] * sres[lr * 129 + n + 1]
                  + c[mi][nj][2] * sres[(lr + 8) * 129 + n]
                  + c[mi][nj][3] * sres[(lr + 8) * 129 + n + 1];
        }
    }
    float cr = blk_reduce256(cross, sred);
    if (tid == 0) atomicAdd(&g_acc[1], (double)cr);
    float qd = blk_reduce256(quad, sred);
    if (tid == 0) atomicAdd(&g_acc[2], (double)qd);
}

__global__ void k_out(float* out, int out_size, int N) {
    int t = threadIdx.x;
    for (int i = t; i < out_size; i += blockDim.x) out[i] = 0.f;
    __syncthreads();
    if (t == 0) {
        double see = g_acc[0], cross = g_acc[1], quad = g_acc[2], r2 = g_acc[3];
        double recon = (see - 2.0 * cross + quad) / ((double)N * (double)DIN);
        double rq = 1.25 * r2 / ((double)N * (double)DH);
        double loss = recon + rq;
        int u[3];
        #pragma unroll
        for (int s = 0; s < 3; s++) {
            int c = 0;
            #pragma unroll
            for (int w = 0; w < 8; w++) c += __popc(g_used[s * 8 + w]);
            u[s] = c;
        }
        if (out_size > 0) out[0] = (float)loss;
        if (out_size > 1) out[1] = (float)recon;
        if (out_size > 2) out[2] = (float)rq;
        if (out_size > 3) out[3] = (float)u[0];
        if (out_size > 4) out[4] = (float)u[1];
        if (out_size > 5) out[5] = (float)u[2];
    }
}

extern "C" void kernel_launch(void* const* d_in, const int* in_sizes, int n_in,
                              void* d_out, int out_size) {
    const float* emb  = (const float*)d_in[0];
    const float* Wenc = (const float*)d_in[1];
    const float* Wdec = (const float*)d_in[2];
    const float* cb0  = (const float*)d_in[3];
    const float* cb1  = (const float*)d_in[4];
    const float* cb2  = (const float*)d_in[5];
    int N = in_sizes[0] / DIN;
    if (N > NMAX) N = NMAX;
    int nb = N / 128;

    cudaFuncSetAttribute(k_gemm1, cudaFuncAttributeMaxDynamicSharedMemorySize, SMEM_G1);
    cudaFuncSetAttribute(k_stage, cudaFuncAttributeMaxDynamicSharedMemorySize, SMEM_ST);
    cudaFuncSetAttribute(k_fin,   cudaFuncAttributeMaxDynamicSharedMemorySize, SMEM_FN);

    k_zero<<<1, 64>>>();
    k_prepB<<<256, 256>>>(Wenc, Wdec);
    k_prepCB<<<768, 128>>>(cb0, cb1, cb2);
    k_cnorm<<<3, 256>>>(cb0, cb1, cb2);
    k_G<<<128, 128>>>(Wdec);
    k_cvtG<<<128, 128>>>();
    k_gemm1<<<dim3(nb, 2), 256, SMEM_G1>>>(emb);
    k_stage<<<nb, 256, SMEM_ST>>>(cb0, 0);
    k_stage<<<nb, 256, SMEM_ST>>>(cb1, 1);
    k_stage<<<nb, 256, SMEM_ST>>>(cb2, 2);
    k_fin<<<nb, 256, SMEM_FN>>>();
    k_out<<<1, 32>>>((float*)d_out, out_size, N);
}